// round 2
// baseline (speedup 1.0000x reference)
#include <cuda_runtime.h>
#include <math.h>

#define NT    256
#define ROWS  16
#define NBLK  128          // 2048/16
#define TSEQ  256
#define FIN   64

typedef unsigned long long u64;

// ---- smem layout (float offsets) ----
#define WP0_N   (128*64*4)
#define WP1_N   (96*32*4)
#define WP2_N   (48*16*4)
#define WP0_OFF 0
#define WP1_OFF (WP0_OFF + WP0_N)      // 32768
#define WP2_OFF (WP1_OFF + WP1_N)      // 45056
#define BP0_OFF (WP2_OFF + WP2_N)      // 48128
#define BP1_OFF (BP0_OFF + 256)        // 48384
#define BP2_OFF (BP1_OFF + 128)        // 48512
#define WDS_OFF (BP2_OFF + 64)         // 48576
#define BDS_OFF (WDS_OFF + 16)         // 48592
#define IN0_OFF (BDS_OFF + 4)          // 48596 (16B aligned)
#define IN0_N   (128*16)               // swizzled [k][16]
#define IN1_OFF (IN0_OFF + IN0_N)      // 50644
#define IN1_N   (96*32)                // swizzled [k][32] (8 slots)
#define IN2_OFF (IN1_OFF + IN1_N)      // 53716
#define IN2_N   (48*16)                // plain [k][16]
#define SMEM_FLOATS (IN2_OFF + IN2_N)  // 54484
#define SMEM_BYTES  (SMEM_FLOATS * 4)  // 217936

// in0 swizzle: addr(k,r) = k*16 + 4*((r>>2) ^ (k&3)) + (r&3)
// in1 swizzle: addr(k,r) = k*32 + 4*((r>>2) ^ (k&7)) + (r&3)
// in2 plain:   addr(k,r) = k*16 + r

__device__ __forceinline__ u64 ffma2(u64 a, u64 b, u64 c) {
    u64 d; asm("fma.rn.f32x2 %0, %1, %2, %3;" : "=l"(d) : "l"(a), "l"(b), "l"(c));
    return d;
}
__device__ __forceinline__ u64 fadd2(u64 a, u64 b) {
    u64 d; asm("add.rn.f32x2 %0, %1, %2;" : "=l"(d) : "l"(a), "l"(b));
    return d;
}
__device__ __forceinline__ u64 dup2(float x) {
    u64 d; asm("mov.b64 %0, {%1, %1};" : "=l"(d) : "f"(x));
    return d;
}
__device__ __forceinline__ float2 unpk(u64 v) {
    float2 r; asm("mov.b64 {%0, %1}, %2;" : "=f"(r.x), "=f"(r.y) : "l"(v));
    return r;
}
__device__ __forceinline__ float sigf(float x) {
    return __fdividef(1.0f, 1.0f + __expf(-x));
}
__device__ __forceinline__ float tanhe(float x) {
    return 2.0f * __fdividef(1.0f, 1.0f + __expf(-2.0f * x)) - 1.0f;
}

__global__ void __launch_bounds__(NT, 1) lstm3_fused_kernel(
    const float* __restrict__ x,
    const float* __restrict__ W0, const float* __restrict__ U0, const float* __restrict__ b0,
    const float* __restrict__ W1, const float* __restrict__ U1, const float* __restrict__ b1,
    const float* __restrict__ W2, const float* __restrict__ U2, const float* __restrict__ b2,
    const float* __restrict__ Wd, const float* __restrict__ bd,
    float* __restrict__ out)
{
    extern __shared__ float sm[];
    const int tid  = threadIdx.x;
    const int row0 = blockIdx.x * ROWS;

    float* wp0 = sm + WP0_OFF;
    float* wp1 = sm + WP1_OFF;
    float* wp2 = sm + WP2_OFF;
    float* bp0 = sm + BP0_OFF;
    float* bp1 = sm + BP1_OFF;
    float* bp2 = sm + BP2_OFF;
    float* wds = sm + WDS_OFF;
    float* bds = sm + BDS_OFF;
    float* in0 = sm + IN0_OFF;
    float* in1 = sm + IN1_OFF;
    float* in2 = sm + IN2_OFF;

    // ---- load + rearrange weights: [k][u][g] float4 per (k,u) ----
    for (int idx = tid; idx < WP0_N; idx += NT) {
        int g = idx & 3, u = (idx >> 2) & 63, k = idx >> 8;
        wp0[idx] = (k < 64) ? W0[k*256 + g*64 + u] : U0[(k-64)*256 + g*64 + u];
    }
    for (int idx = tid; idx < WP1_N; idx += NT) {
        int g = idx & 3, u = (idx >> 2) & 31, k = idx >> 7;
        wp1[idx] = (k < 64) ? W1[k*128 + g*32 + u] : U1[(k-64)*128 + g*32 + u];
    }
    for (int idx = tid; idx < WP2_N; idx += NT) {
        int g = idx & 3, u = (idx >> 2) & 15, k = idx >> 6;
        wp2[idx] = (k < 32) ? W2[k*64 + g*16 + u] : U2[(k-32)*64 + g*16 + u];
    }
    if (tid < 256) bp0[tid] = b0[(tid & 3)*64 + (tid >> 2)];
    if (tid < 128) bp1[tid] = b1[(tid & 3)*32 + (tid >> 2)];
    if (tid < 64)  bp2[tid] = b2[(tid & 3)*16 + (tid >> 2)];
    if (tid < 16)  wds[tid] = Wd[tid];
    if (tid == 0)  bds[0]   = bd[0];
    for (int idx = tid; idx < IN0_N; idx += NT) in0[idx] = 0.0f;
    for (int idx = tid; idx < IN1_N; idx += NT) in1[idx] = 0.0f;
    for (int idx = tid; idx < IN2_N; idx += NT) in2[idx] = 0.0f;
    __syncthreads();

    const float4* wp0v = reinterpret_cast<const float4*>(wp0);
    const float4* wp1v = reinterpret_cast<const float4*>(wp1);

    // ---- thread mappings ----
    const int u0  = tid >> 2, kc0 = tid & 3;            // L0: 64 units x 4 k-chunks
    const int b00 = kc0 & 1, b01 = (kc0 >> 1) & 1;
    const int cown0 = 2*b00 + b01;                       // final chunk owned (rows 4*cown0..+3)

    const int u1  = tid >> 3, kc1 = tid & 7;            // L1: 32 units x 8 k-chunks
    const int b10 = kc1 & 1, b11 = (kc1 >> 1) & 1, b12 = (kc1 >> 2) & 1;
    const int rpo1 = 4*b10 + 2*b11 + b12;                // final row-pair owned (rows 2*rpo1..+1)

    const int u2 = tid & 15, r2 = tid >> 4;             // L2: 16 units x 16 rows

    const float4 bias0 = reinterpret_cast<const float4*>(bp0)[u0];
    const float4 bias1 = reinterpret_cast<const float4*>(bp1)[u1];
    const float4 bias2 = reinterpret_cast<const float4*>(bp2)[u2];

    float c0[4] = {0.f,0.f,0.f,0.f};
    float c1[2] = {0.f,0.f};
    float c2v   = 0.f;

    // x staging: thread loads rows 4*ra..4*ra+3, feature f0
    const int f0 = tid & 63;
    const int ra = tid >> 6;
    const size_t xbase = (size_t)(row0 + 4*ra) * (TSEQ * FIN) + f0;
    float xr[4];
#pragma unroll
    for (int j = 0; j < 4; ++j)
        xr[j] = x[xbase + (size_t)j * (TSEQ*FIN)];
    float* xsts = in0 + f0*16 + 4*(ra ^ (f0 & 3));

    // precomputed chunk offsets for broadcast h loads
    const int o00 = 4*(0 ^ kc0), o01 = 4*(1 ^ kc0), o02 = 4*(2 ^ kc0), o03 = 4*(3 ^ kc0);
    const int o10 = 4*(0 ^ kc1), o11 = 4*(1 ^ kc1), o12 = 4*(2 ^ kc1), o13 = 4*(3 ^ kc1);

    for (int t = 0; t < TSEQ; ++t) {
        // ---- stage x_t ----
        *reinterpret_cast<float4*>(xsts) = make_float4(xr[0], xr[1], xr[2], xr[3]);
        __syncthreads();

        // prefetch x_{t+1}
        if (t + 1 < TSEQ) {
#pragma unroll
            for (int j = 0; j < 4; ++j)
                xr[j] = x[xbase + (size_t)(t+1)*FIN + (size_t)j * (TSEQ*FIN)];
        }

        // ================= Layer 0: K=128 (k = 4*kk + kc0), H=64 =================
        u64 a0[4][8];
#pragma unroll
        for (int g = 0; g < 4; ++g)
#pragma unroll
            for (int rp = 0; rp < 8; ++rp) a0[g][rp] = 0ull;
        {
            const float4* wc = wp0v + kc0*64 + u0;   // advance 4 k -> +256 float4
            const float*  hb = in0 + kc0*16;         // advance 4 k -> +64 floats
#pragma unroll 2
            for (int kk = 0; kk < 32; ++kk) {
                float4 w = wc[kk*256];
                u64 wg[4] = { dup2(w.x), dup2(w.y), dup2(w.z), dup2(w.w) };
                const float* h = hb + kk*64;
                ulonglong2 hA = *reinterpret_cast<const ulonglong2*>(h + o00);
                ulonglong2 hB = *reinterpret_cast<const ulonglong2*>(h + o01);
                ulonglong2 hC = *reinterpret_cast<const ulonglong2*>(h + o02);
                ulonglong2 hD = *reinterpret_cast<const ulonglong2*>(h + o03);
#pragma unroll
                for (int g = 0; g < 4; ++g) {
                    a0[g][0] = ffma2(wg[g], hA.x, a0[g][0]);
                    a0[g][1] = ffma2(wg[g], hA.y, a0[g][1]);
                    a0[g][2] = ffma2(wg[g], hB.x, a0[g][2]);
                    a0[g][3] = ffma2(wg[g], hB.y, a0[g][3]);
                    a0[g][4] = ffma2(wg[g], hC.x, a0[g][4]);
                    a0[g][5] = ffma2(wg[g], hC.y, a0[g][5]);
                    a0[g][6] = ffma2(wg[g], hD.x, a0[g][6]);
                    a0[g][7] = ffma2(wg[g], hD.y, a0[g][7]);
                }
            }
        }
        // ---- reduce over kc0 (xor 1, then xor 2) ----
        u64 redA[4][4];   // 2 kept chunks (h=0,1) x 2 pairs
#pragma unroll
        for (int g = 0; g < 4; ++g)
#pragma unroll
            for (int h = 0; h < 2; ++h)
#pragma unroll
                for (int p = 0; p < 2; ++p) {
                    u64 snd = b00 ? a0[g][2*h + p]       : a0[g][2*(2+h) + p];
                    u64 rcv = __shfl_xor_sync(0xffffffffu, snd, 1);
                    u64 kp  = b00 ? a0[g][2*(2+h) + p]   : a0[g][2*h + p];
                    redA[g][2*h + p] = fadd2(kp, rcv);
                }
        u64 fin0[4][2];
#pragma unroll
        for (int g = 0; g < 4; ++g)
#pragma unroll
            for (int p = 0; p < 2; ++p) {
                u64 snd = b01 ? redA[g][0 + p] : redA[g][2 + p];
                u64 rcv = __shfl_xor_sync(0xffffffffu, snd, 2);
                u64 kp  = b01 ? redA[g][2 + p] : redA[g][0 + p];
                fin0[g][p] = fadd2(kp, rcv);
            }
        // ---- activations for rows 4*cown0 .. +3 ----
        float h0v[4];
#pragma unroll
        for (int p = 0; p < 2; ++p) {
            float2 vi = unpk(fin0[0][p]);
            float2 vf = unpk(fin0[1][p]);
            float2 vg = unpk(fin0[2][p]);
            float2 vo = unpk(fin0[3][p]);
            {
                float ig = sigf(vi.x + bias0.x);
                float fg = sigf(vf.x + bias0.y);
                float gg = tanhe(vg.x + bias0.z);
                float og = sigf(vo.x + bias0.w);
                c0[2*p]   = fg * c0[2*p] + ig * gg;
                h0v[2*p]  = og * tanhe(c0[2*p]);
            }
            {
                float ig = sigf(vi.y + bias0.x);
                float fg = sigf(vf.y + bias0.y);
                float gg = tanhe(vg.y + bias0.z);
                float og = sigf(vo.y + bias0.w);
                c0[2*p+1]  = fg * c0[2*p+1] + ig * gg;
                h0v[2*p+1] = og * tanhe(c0[2*p+1]);
            }
        }
        __syncthreads();   // all in0 reads done
        {
            float4 hv = make_float4(h0v[0], h0v[1], h0v[2], h0v[3]);
            // recurrent (in0, k=64+u0) and layer1 input (in1, k=u0)
            *reinterpret_cast<float4*>(in0 + (64+u0)*16 + 4*(cown0 ^ (u0 & 3))) = hv;
            *reinterpret_cast<float4*>(in1 + u0*32      + 4*(cown0 ^ (u0 & 7))) = hv;
        }
        __syncthreads();

        // ================= Layer 1: K=96 (k = 8*kk + kc1), H=32 =================
        u64 a1[4][8];
#pragma unroll
        for (int g = 0; g < 4; ++g)
#pragma unroll
            for (int rp = 0; rp < 8; ++rp) a1[g][rp] = 0ull;
        {
            const float4* wc = wp1v + kc1*32 + u1;   // advance 8 k -> +256 float4
            const float*  hb = in1 + kc1*32;         // advance 8 k -> +256 floats
#pragma unroll 2
            for (int kk = 0; kk < 12; ++kk) {
                float4 w = wc[kk*256];
                u64 wg[4] = { dup2(w.x), dup2(w.y), dup2(w.z), dup2(w.w) };
                const float* h = hb + kk*256;
                ulonglong2 hA = *reinterpret_cast<const ulonglong2*>(h + o10);
                ulonglong2 hB = *reinterpret_cast<const ulonglong2*>(h + o11);
                ulonglong2 hC = *reinterpret_cast<const ulonglong2*>(h + o12);
                ulonglong2 hD = *reinterpret_cast<const ulonglong2*>(h + o13);
#pragma unroll
                for (int g = 0; g < 4; ++g) {
                    a1[g][0] = ffma2(wg[g], hA.x, a1[g][0]);
                    a1[g][1] = ffma2(wg[g], hA.y, a1[g][1]);
                    a1[g][2] = ffma2(wg[g], hB.x, a1[g][2]);
                    a1[g][3] = ffma2(wg[g], hB.y, a1[g][3]);
                    a1[g][4] = ffma2(wg[g], hC.x, a1[g][4]);
                    a1[g][5] = ffma2(wg[g], hC.y, a1[g][5]);
                    a1[g][6] = ffma2(wg[g], hD.x, a1[g][6]);
                    a1[g][7] = ffma2(wg[g], hD.y, a1[g][7]);
                }
            }
        }
        // ---- reduce over kc1 (xor 1, 2, 4) ----
        u64 r1A[4][4];
#pragma unroll
        for (int g = 0; g < 4; ++g)
#pragma unroll
            for (int i = 0; i < 4; ++i) {
                u64 snd = b10 ? a1[g][i]     : a1[g][4+i];
                u64 rcv = __shfl_xor_sync(0xffffffffu, snd, 1);
                u64 kp  = b10 ? a1[g][4+i]   : a1[g][i];
                r1A[g][i] = fadd2(kp, rcv);
            }
        u64 r1B[4][2];
#pragma unroll
        for (int g = 0; g < 4; ++g)
#pragma unroll
            for (int i = 0; i < 2; ++i) {
                u64 snd = b11 ? r1A[g][i]    : r1A[g][2+i];
                u64 rcv = __shfl_xor_sync(0xffffffffu, snd, 2);
                u64 kp  = b11 ? r1A[g][2+i]  : r1A[g][i];
                r1B[g][i] = fadd2(kp, rcv);
            }
        u64 fin1[4];
#pragma unroll
        for (int g = 0; g < 4; ++g) {
            u64 snd = b12 ? r1B[g][0] : r1B[g][1];
            u64 rcv = __shfl_xor_sync(0xffffffffu, snd, 4);
            u64 kp  = b12 ? r1B[g][1] : r1B[g][0];
            fin1[g] = fadd2(kp, rcv);
        }
        // ---- activations for rows 2*rpo1, 2*rpo1+1 ----
        float h1v[2];
        {
            float2 vi = unpk(fin1[0]);
            float2 vf = unpk(fin1[1]);
            float2 vg = unpk(fin1[2]);
            float2 vo = unpk(fin1[3]);
            {
                float ig = sigf(vi.x + bias1.x);
                float fg = sigf(vf.x + bias1.y);
                float gg = tanhe(vg.x + bias1.z);
                float og = sigf(vo.x + bias1.w);
                c1[0]  = fg * c1[0] + ig * gg;
                h1v[0] = og * tanhe(c1[0]);
            }
            {
                float ig = sigf(vi.y + bias1.x);
                float fg = sigf(vf.y + bias1.y);
                float gg = tanhe(vg.y + bias1.z);
                float og = sigf(vo.y + bias1.w);
                c1[1]  = fg * c1[1] + ig * gg;
                h1v[1] = og * tanhe(c1[1]);
            }
        }
        __syncthreads();   // all in1 reads done
        {
            float2 hv = make_float2(h1v[0], h1v[1]);
            // recurrent (in1, k=64+u1); ((64+u1)&7) == (u1&7)
            *reinterpret_cast<float2*>(in1 + (64+u1)*32 + 4*((rpo1 >> 1) ^ (u1 & 7)) + 2*(rpo1 & 1)) = hv;
            // layer2 input (in2, k=u1, plain)
            *reinterpret_cast<float2*>(in2 + u1*16 + 2*rpo1) = hv;
        }
        __syncthreads();

        // ================= Layer 2: K=48, H=16 (plain mapping) =================
        u64 aif = 0ull, ago = 0ull;
        {
            const ulonglong2* wc = reinterpret_cast<const ulonglong2*>(wp2) + u2;
            const float*      hb = in2 + r2;
#pragma unroll 4
            for (int k = 0; k < 48; ++k) {
                ulonglong2 w = wc[k*16];
                u64 hd = dup2(hb[k*16]);
                aif = ffma2(w.x, hd, aif);
                ago = ffma2(w.y, hd, ago);
            }
        }
        float h2val;
        {
            float2 zif = unpk(aif);
            float2 zgo = unpk(ago);
            float ig = sigf(zif.x + bias2.x);
            float fg = sigf(zif.y + bias2.y);
            float gg = tanhe(zgo.x + bias2.z);
            float og = sigf(zgo.y + bias2.w);
            c2v   = fg * c2v + ig * gg;
            h2val = og * tanhe(c2v);
        }
        __syncthreads();   // all in2 reads done
        in2[(32 + u2)*16 + r2] = h2val;
        __syncthreads();
    }

    // ---- Dense head ----
    if (tid < 16) {
        float s = bds[0];
#pragma unroll
        for (int j = 0; j < 16; ++j)
            s += in2[(32 + j)*16 + tid] * wds[j];
        out[row0 + tid] = s;
    }
}

extern "C" void kernel_launch(void* const* d_in, const int* in_sizes, int n_in,
                              void* d_out, int out_size)
{
    (void)in_sizes; (void)n_in; (void)out_size;
    const float* x  = (const float*)d_in[0];
    const float* W0 = (const float*)d_in[1];
    const float* U0 = (const float*)d_in[2];
    const float* b0 = (const float*)d_in[3];
    const float* W1 = (const float*)d_in[4];
    const float* U1 = (const float*)d_in[5];
    const float* b1 = (const float*)d_in[6];
    const float* W2 = (const float*)d_in[7];
    const float* U2 = (const float*)d_in[8];
    const float* b2 = (const float*)d_in[9];
    const float* Wd = (const float*)d_in[10];
    const float* bd = (const float*)d_in[11];
    float* out = (float*)d_out;

    cudaFuncSetAttribute(lstm3_fused_kernel,
                         cudaFuncAttributeMaxDynamicSharedMemorySize, SMEM_BYTES);
    lstm3_fused_kernel<<<NBLK, NT, SMEM_BYTES>>>(
        x, W0, U0, b0, W1, U1, b1, W2, U2, b2, Wd, bd, out);
}

// round 3
// speedup vs baseline: 1.0471x; 1.0471x over previous
#include <cuda_runtime.h>

#define NT    256
#define ROWS  16
#define NBLK  128          // 2048/16
#define TSEQ  256
#define FIN   64

typedef unsigned long long u64;

// ---- smem layout (float offsets) ----
#define WP0_N   (128*64*4)
#define WP1_N   (96*32*4)
#define WP2_N   (48*16*4)
#define WP0_OFF 0
#define WP1_OFF 32768
#define WP2_OFF 45056
#define BP0_OFF 48128
#define BP1_OFF 48384
#define BP2_OFF 48512
#define WDS_OFF 48576
#define BDS_OFF 48592
#define IN0_OFF 48608            // 48608*4 = 194432 = 1519*128 -> 128B aligned
#define IN0_STR 36               // floats per k-row (row-duplicated: 16 rows x2 + pad)
#define IN0_N   (128*IN0_STR)    // 4608
#define IN1_OFF (IN0_OFF + IN0_N)   // 53216
#define IN1_N   (96*32)             // 3072 (stride 32)
#define IN2_OFF (IN1_OFF + IN1_N)   // 56288
#define IN2_N   (48*32)             // 1536 (stride 32)
#define SMEM_FLOATS (IN2_OFF + IN2_N)  // 57824
#define SMEM_BYTES  (SMEM_FLOATS * 4)  // 231296  (< 232448 limit)

__device__ __forceinline__ u64 ffma2(u64 a, u64 b, u64 c) {
    u64 d; asm("fma.rn.f32x2 %0, %1, %2, %3;" : "=l"(d) : "l"(a), "l"(b), "l"(c));
    return d;
}
__device__ __forceinline__ u64 dup2(float x) {
    u64 d; asm("mov.b64 %0, {%1, %1};" : "=l"(d) : "f"(x));
    return d;
}
__device__ __forceinline__ float2 unpk(u64 v) {
    float2 r; asm("mov.b64 {%0, %1}, %2;" : "=f"(r.x), "=f"(r.y) : "l"(v));
    return r;
}
__device__ __forceinline__ float sigf(float x) {
    return __fdividef(1.0f, 1.0f + __expf(-x));
}
__device__ __forceinline__ float tanhe(float x) {
    return 2.0f * __fdividef(1.0f, 1.0f + __expf(-2.0f * x)) - 1.0f;
}

__global__ void __launch_bounds__(NT, 1) lstm3_fused_kernel(
    const float* __restrict__ x,
    const float* __restrict__ W0, const float* __restrict__ U0, const float* __restrict__ b0,
    const float* __restrict__ W1, const float* __restrict__ U1, const float* __restrict__ b1,
    const float* __restrict__ W2, const float* __restrict__ U2, const float* __restrict__ b2,
    const float* __restrict__ Wd, const float* __restrict__ bd,
    float* __restrict__ out)
{
    extern __shared__ float sm[];
    const int tid  = threadIdx.x;
    const int row0 = blockIdx.x * ROWS;

    float* wp0 = sm + WP0_OFF;
    float* wp1 = sm + WP1_OFF;
    float* wp2 = sm + WP2_OFF;
    float* bp0 = sm + BP0_OFF;
    float* bp1 = sm + BP1_OFF;
    float* bp2 = sm + BP2_OFF;
    float* wds = sm + WDS_OFF;
    float* bds = sm + BDS_OFF;
    float* in0 = sm + IN0_OFF;   // [k=128][36] row-dup: value r at 2r,2r+1 ; k<64 x_t, k>=64 h0
    float* in1 = sm + IN1_OFF;   // [k=96][32] row-dup : k<64 h0, k>=64 h1
    float* in2 = sm + IN2_OFF;   // [k=48][32] row-dup : k<32 h1, k>=32 h2

    // ---- load + rearrange weights: [k][u][g] (g order i,f,g,o) ----
    for (int idx = tid; idx < WP0_N; idx += NT) {
        int g = idx & 3, u = (idx >> 2) & 63, k = idx >> 8;
        wp0[idx] = (k < 64) ? W0[k*256 + g*64 + u] : U0[(k-64)*256 + g*64 + u];
    }
    for (int idx = tid; idx < WP1_N; idx += NT) {
        int g = idx & 3, u = (idx >> 2) & 31, k = idx >> 7;
        wp1[idx] = (k < 64) ? W1[k*128 + g*32 + u] : U1[(k-64)*128 + g*32 + u];
    }
    for (int idx = tid; idx < WP2_N; idx += NT) {
        int g = idx & 3, u = (idx >> 2) & 15, k = idx >> 6;
        wp2[idx] = (k < 32) ? W2[k*64 + g*16 + u] : U2[(k-32)*64 + g*16 + u];
    }
    if (tid < 256) bp0[tid] = b0[(tid & 3)*64 + (tid >> 2)];
    if (tid < 128) bp1[tid] = b1[(tid & 3)*32 + (tid >> 2)];
    if (tid < 64)  bp2[tid] = b2[(tid & 3)*16 + (tid >> 2)];
    if (tid < 16)  wds[tid] = Wd[tid];
    if (tid == 0)  bds[0]   = bd[0];
    for (int idx = tid; idx < IN0_N; idx += NT) in0[idx] = 0.0f;
    for (int idx = tid; idx < IN1_N; idx += NT) in1[idx] = 0.0f;
    for (int idx = tid; idx < IN2_N; idx += NT) in2[idx] = 0.0f;
    __syncthreads();

    // ---- thread mappings: warp covers few units x all rowgroups ----
    const int wrp = tid >> 5, lan = tid & 31;
    const int u0 = wrp*8 + (lan & 7), rg0 = lan >> 3;   // L0: unit, rows 4*rg0..+3
    const int u1 = wrp*4 + (lan & 3), rg1 = lan >> 2;   // L1: unit, rows 2*rg1..+1
    const int u2 = wrp*2 + (lan & 1), r2  = lan >> 1;   // L2: unit, row r2

    const ulonglong2 bias0 = reinterpret_cast<const ulonglong2*>(bp0)[u0]; // {bi,bf},{bg,bo}
    const ulonglong2 bias1 = reinterpret_cast<const ulonglong2*>(bp1)[u1];
    const ulonglong2 bias2 = reinterpret_cast<const ulonglong2*>(bp2)[u2];

    const ulonglong2* w0v = reinterpret_cast<const ulonglong2*>(wp0) + u0; // [k*64]
    const ulonglong2* w1v = reinterpret_cast<const ulonglong2*>(wp1) + u1; // [k*32]
    const ulonglong2* w2v = reinterpret_cast<const ulonglong2*>(wp2) + u2; // [k*16]
    const float* h0b = in0 + 8*rg0;
    const float* h1b = in1 + 4*rg1;
    const float* h2b = in2 + 2*r2;

    float c0[4] = {0.f,0.f,0.f,0.f};
    float c1[2] = {0.f,0.f};
    float c2v   = 0.f;

    // x staging: thread stages rows 4*ra..+3 of feature f0
    const int f0 = tid & 63;
    const int ra = tid >> 6;
    const size_t xbase = (size_t)(row0 + 4*ra) * (TSEQ * FIN) + f0;
    float* xsts = in0 + f0*IN0_STR + 8*ra;
    float xr[4];
#pragma unroll
    for (int j = 0; j < 4; ++j)
        xr[j] = x[xbase + (size_t)j * (TSEQ*FIN)];
    // stage x_0
    *reinterpret_cast<float4*>(xsts)     = make_float4(xr[0], xr[0], xr[1], xr[1]);
    *reinterpret_cast<float4*>(xsts + 4) = make_float4(xr[2], xr[2], xr[3], xr[3]);
    __syncthreads();

    for (int t = 0; t < TSEQ; ++t) {
        // prefetch x_{t+1} into regs (consumed mid-iteration)
        if (t + 1 < TSEQ) {
#pragma unroll
            for (int j = 0; j < 4; ++j)
                xr[j] = x[xbase + (size_t)(t+1)*FIN + (size_t)j * (TSEQ*FIN)];
        }

        // ================= Layer 0: K=128, 4 rows x {if,go} =================
        u64 a0[4][2];
#pragma unroll
        for (int r = 0; r < 4; ++r) { a0[r][0] = bias0.x; a0[r][1] = bias0.y; }
#pragma unroll 4
        for (int k = 0; k < 128; ++k) {
            ulonglong2 w = w0v[k*64];
            const float* h = h0b + k*IN0_STR;
            ulonglong2 hA = *reinterpret_cast<const ulonglong2*>(h);     // {r0,r0},{r1,r1}
            ulonglong2 hB = *reinterpret_cast<const ulonglong2*>(h + 4); // {r2,r2},{r3,r3}
            a0[0][0] = ffma2(w.x, hA.x, a0[0][0]); a0[0][1] = ffma2(w.y, hA.x, a0[0][1]);
            a0[1][0] = ffma2(w.x, hA.y, a0[1][0]); a0[1][1] = ffma2(w.y, hA.y, a0[1][1]);
            a0[2][0] = ffma2(w.x, hB.x, a0[2][0]); a0[2][1] = ffma2(w.y, hB.x, a0[2][1]);
            a0[3][0] = ffma2(w.x, hB.y, a0[3][0]); a0[3][1] = ffma2(w.y, hB.y, a0[3][1]);
        }
        float h0v[4];
#pragma unroll
        for (int r = 0; r < 4; ++r) {
            float2 zif = unpk(a0[r][0]);
            float2 zgo = unpk(a0[r][1]);
            float ig = sigf(zif.x);
            float fg = sigf(zif.y);
            float gg = tanhe(zgo.x);
            float og = sigf(zgo.y);
            c0[r]  = fg * c0[r] + ig * gg;
            h0v[r] = og * tanhe(c0[r]);
        }
        __syncthreads();   // all in0 reads done (B)
        {
            float4 hv01 = make_float4(h0v[0], h0v[0], h0v[1], h0v[1]);
            float4 hv23 = make_float4(h0v[2], h0v[2], h0v[3], h0v[3]);
            float* p0 = in0 + (64 + u0)*IN0_STR + 8*rg0;   // recurrent for t+1
            *reinterpret_cast<float4*>(p0)     = hv01;
            *reinterpret_cast<float4*>(p0 + 4) = hv23;
            float* p1 = in1 + u0*32 + 8*rg0;               // layer1 input this step
            *reinterpret_cast<float4*>(p1)     = hv01;
            *reinterpret_cast<float4*>(p1 + 4) = hv23;
        }
        // stage x_{t+1} (x region free since sync B)
        if (t + 1 < TSEQ) {
            *reinterpret_cast<float4*>(xsts)     = make_float4(xr[0], xr[0], xr[1], xr[1]);
            *reinterpret_cast<float4*>(xsts + 4) = make_float4(xr[2], xr[2], xr[3], xr[3]);
        }
        __syncthreads();   // (C)

        // ================= Layer 1: K=96, 2 rows x {if,go} =================
        u64 a1[2][2];
        a1[0][0] = bias1.x; a1[0][1] = bias1.y;
        a1[1][0] = bias1.x; a1[1][1] = bias1.y;
#pragma unroll 4
        for (int k = 0; k < 96; ++k) {
            ulonglong2 w = w1v[k*32];
            ulonglong2 h = *reinterpret_cast<const ulonglong2*>(h1b + k*32); // {r0,r0},{r1,r1}
            a1[0][0] = ffma2(w.x, h.x, a1[0][0]); a1[0][1] = ffma2(w.y, h.x, a1[0][1]);
            a1[1][0] = ffma2(w.x, h.y, a1[1][0]); a1[1][1] = ffma2(w.y, h.y, a1[1][1]);
        }
        float h1v[2];
#pragma unroll
        for (int r = 0; r < 2; ++r) {
            float2 zif = unpk(a1[r][0]);
            float2 zgo = unpk(a1[r][1]);
            float ig = sigf(zif.x);
            float fg = sigf(zif.y);
            float gg = tanhe(zgo.x);
            float og = sigf(zgo.y);
            c1[r]  = fg * c1[r] + ig * gg;
            h1v[r] = og * tanhe(c1[r]);
        }
        __syncthreads();   // all in1 reads done (D)
        {
            float4 hv = make_float4(h1v[0], h1v[0], h1v[1], h1v[1]);
            *reinterpret_cast<float4*>(in1 + (64 + u1)*32 + 4*rg1) = hv;  // recurrent
            *reinterpret_cast<float4*>(in2 + u1*32        + 4*rg1) = hv;  // layer2 input
        }
        __syncthreads();   // (E)

        // ================= Layer 2: K=48, 1 row x {if,go} =================
        u64 aif = bias2.x, ago = bias2.y;
#pragma unroll 4
        for (int k = 0; k < 48; ++k) {
            ulonglong2 w = w2v[k*16];
            u64 hd = *reinterpret_cast<const u64*>(h2b + k*32);  // {h,h}
            aif = ffma2(w.x, hd, aif);
            ago = ffma2(w.y, hd, ago);
        }
        float h2val;
        {
            float2 zif = unpk(aif);
            float2 zgo = unpk(ago);
            float ig = sigf(zif.x);
            float fg = sigf(zif.y);
            float gg = tanhe(zgo.x);
            float og = sigf(zgo.y);
            c2v   = fg * c2v + ig * gg;
            h2val = og * tanhe(c2v);
        }
        __syncthreads();   // all in2 reads done (F)
        *reinterpret_cast<u64*>(in2 + (32 + u2)*32 + 2*r2) = dup2(h2val);
        // h2 store visible to next L2 read via next iteration's syncs (B..E)
    }
    __syncthreads();

    // ---- Dense head ----
    if (tid < 16) {
        float s = bds[0];
#pragma unroll
        for (int j = 0; j < 16; ++j)
            s += in2[(32 + j)*32 + 2*tid] * wds[j];
        out[row0 + tid] = s;
    }
}

extern "C" void kernel_launch(void* const* d_in, const int* in_sizes, int n_in,
                              void* d_out, int out_size)
{
    (void)in_sizes; (void)n_in; (void)out_size;
    const float* x  = (const float*)d_in[0];
    const float* W0 = (const float*)d_in[1];
    const float* U0 = (const float*)d_in[2];
    const float* b0 = (const float*)d_in[3];
    const float* W1 = (const float*)d_in[4];
    const float* U1 = (const float*)d_in[5];
    const float* b1 = (const float*)d_in[6];
    const float* W2 = (const float*)d_in[7];
    const float* U2 = (const float*)d_in[8];
    const float* b2 = (const float*)d_in[9];
    const float* Wd = (const float*)d_in[10];
    const float* bd = (const float*)d_in[11];
    float* out = (float*)d_out;

    cudaFuncSetAttribute(lstm3_fused_kernel,
                         cudaFuncAttributeMaxDynamicSharedMemorySize, SMEM_BYTES);
    lstm3_fused_kernel<<<NBLK, NT, SMEM_BYTES>>>(
        x, W0, U0, b0, W1, U1, b1, W2, U2, b2, Wd, bd, out);
}